// round 1
// baseline (speedup 1.0000x reference)
#include <cuda_runtime.h>
#include <cuda_bf16.h>
#include <math.h>

// ---------------- problem constants ----------------
#define CB0   8
#define CCIN  3
#define CGH   17
#define CGW   90
#define CPH   20
#define CPW   8
#define CHID  128
#define CNL   4
#define CNH   4
#define CHD   64
#define CNST  128
#define CDIN  256      // NH*HD
#define CCONVD 512     // DIN + 2*NSTATE
#define CPROJ 772      // DIN + CONVD + NH
#define CL    1530     // GH*GW
#define CBZ   16       // 2*B0
#define CPATCH 480     // CIN*PH*PW
#define CEPS  1e-5f

#define M_FWD  (CB0*CL)    // 12240
#define M_ALL  (CBZ*CL)    // 24480

// ---------------- scratch (static device globals; no runtime alloc) ----------------
__device__ float g_h   [CBZ*CL*CHID];    // residual stream
__device__ float g_u   [CBZ*CL*CHID];    // normed / reused temp
__device__ float g_proj[CBZ*CL*CPROJ];   // in_proj out (also patch matrix & r2 out)
__device__ float g_xc  [CBZ*CL*CCONVD]; // conv+silu out
__device__ float g_dt  [CBZ*CL*CNH];
__device__ float g_dA  [CBZ*CL*CNH];
__device__ float g_y   [CBZ*CL*CDIN];    // scan out (also seq buffer)
__device__ float g_g   [CBZ*CL*CDIN];    // gated+normed
__device__ float g_m   [CB0*CL*CHID];    // merged fwd/bwd

// ---------------- generic tiled fp32 GEMM: C[M,N] = A[M,K] @ W[N,K]^T + bias ----------------
// MODE 0: +bias;  MODE 1: +bias + residual R;  MODE 2: +bias then exact GELU
template<int MODE>
__global__ void __launch_bounds__(256, 2)
gemm_kernel(const float* __restrict__ A, const float* __restrict__ W,
            const float* __restrict__ bias, const float* __restrict__ R,
            float* __restrict__ C, int M, int N, int K)
{
    __shared__ float As[128][16];   // [m][k] — conflict-free stores, broadcast reads
    __shared__ float Ws[16][68];    // [k][n] padded to 68 (16B-aligned rows, 2-way store conflicts)
    const int tid  = threadIdx.x;
    const int row0 = blockIdx.y * 128;
    const int col0 = blockIdx.x * 64;
    const int tx   = tid & 15;   // N dir: cols tx*4 .. +4
    const int ty   = tid >> 4;   // M dir: rows ty*8 .. +8

    float acc[8][4];
#pragma unroll
    for (int i = 0; i < 8; i++)
#pragma unroll
        for (int j = 0; j < 4; j++) acc[i][j] = 0.f;

    const int ktiles = K >> 4;
    for (int kt = 0; kt < ktiles; kt++) {
        const int k0 = kt << 4;
        // load A tile (128x16), 8 elems/thread, coalesced-in-16 reads, linear SMEM writes
#pragma unroll
        for (int u = 0; u < 8; u++) {
            int idx = tid + u * 256;
            int kk = idx & 15, mm = idx >> 4;
            int gr = row0 + mm;
            As[mm][kk] = (gr < M) ? A[(size_t)gr * K + k0 + kk] : 0.f;
        }
        // load W tile (64x16 -> [k][n]), 4 elems/thread
#pragma unroll
        for (int u = 0; u < 4; u++) {
            int idx = tid + u * 256;
            int kk = idx & 15, nn = idx >> 4;
            int gc = col0 + nn;
            Ws[kk][nn] = (gc < N) ? W[(size_t)gc * K + k0 + kk] : 0.f;
        }
        __syncthreads();
#pragma unroll
        for (int kk = 0; kk < 16; kk++) {
            float4 wv = *reinterpret_cast<const float4*>(&Ws[kk][tx << 2]);
            float a[8];
#pragma unroll
            for (int i = 0; i < 8; i++) a[i] = As[(ty << 3) + i][kk];
#pragma unroll
            for (int i = 0; i < 8; i++) {
                acc[i][0] += a[i] * wv.x;
                acc[i][1] += a[i] * wv.y;
                acc[i][2] += a[i] * wv.z;
                acc[i][3] += a[i] * wv.w;
            }
        }
        __syncthreads();
    }
#pragma unroll
    for (int i = 0; i < 8; i++) {
        int gr = row0 + (ty << 3) + i;
        if (gr >= M) continue;
#pragma unroll
        for (int j = 0; j < 4; j++) {
            int gc = col0 + (tx << 2) + j;
            if (gc >= N) continue;
            float v = acc[i][j] + bias[gc];
            if (MODE == 1) v += R[(size_t)gr * N + gc];
            if (MODE == 2) v = 0.5f * v * (1.f + erff(v * 0.70710678118654752f));
            C[(size_t)gr * N + gc] = v;
        }
    }
}

// ---------------- patch gather: Apat[12240][480] ----------------
__global__ void gather_patches(const float* __restrict__ x, float* __restrict__ Apat)
{
    int idx = blockIdx.x * blockDim.x + threadIdx.x;
    if (idx >= M_FWD * CPATCH) return;
    int col = idx % CPATCH;
    int row = idx / CPATCH;
    int c = col / 160, rem = col % 160;
    int p = rem >> 3, q = rem & 7;
    int b = row / CL, l = row % CL;
    int i = l / CGW, j = l % CGW;
    Apat[idx] = x[(((size_t)b * CCIN + c) * 340 + (i * CPH + p)) * 720 + (j * CPW + q)];
}

// ---------------- build h: seq + gain channel, forward + reversed ----------------
__global__ void build_h(const float* __restrict__ seq /*12240 x 127*/, float* __restrict__ h)
{
    int idx = blockIdx.x * blockDim.x + threadIdx.x;
    if (idx >= CB0 * CL * CHID) return;
    int d = idx & 127;
    int l = (idx >> 7) % CL;
    int b = idx / (CL * CHID);
    float v;
    if (d < 127) v = seq[(size_t)(b * CL + l) * 127 + d];
    else         v = (float)(l / CGW) * (1.f / 16.f);
    h[idx] = v;
    h[(size_t)(CB0 + b) * CL * CHID + (size_t)(CL - 1 - l) * CHID + d] = v;
}

// ---------------- RMSNorm over 128 (warp per row) ----------------
__global__ void rmsnorm_kernel(const float* __restrict__ in, const float* __restrict__ w,
                               float* __restrict__ out, int rows)
{
    int warp = blockIdx.x * (blockDim.x >> 5) + (threadIdx.x >> 5);
    if (warp >= rows) return;
    int lane = threadIdx.x & 31;
    float4 v = reinterpret_cast<const float4*>(in + (size_t)warp * CHID)[lane];
    float ss = v.x * v.x + v.y * v.y + v.z * v.z + v.w * v.w;
#pragma unroll
    for (int o = 16; o; o >>= 1) ss += __shfl_xor_sync(0xffffffffu, ss, o);
    float sc = rsqrtf(ss * (1.f / 128.f) + CEPS);
    float4 wv = reinterpret_cast<const float4*>(w)[lane];
    float4 ov = make_float4(v.x * sc * wv.x, v.y * sc * wv.y, v.z * sc * wv.z, v.w * sc * wv.w);
    reinterpret_cast<float4*>(out + (size_t)warp * CHID)[lane] = ov;
}

// ---------------- depthwise causal conv(K=4) + SiLU ----------------
__global__ void conv_kernel(const float* __restrict__ proj, const float* __restrict__ cw,
                            const float* __restrict__ cb, float* __restrict__ xc)
{
    int idx = blockIdx.x * blockDim.x + threadIdx.x;
    if (idx >= CBZ * CL * CCONVD) return;
    int c = idx & (CCONVD - 1);
    int l = (idx >> 9) % CL;
    int b = idx / (CL * CCONVD);
    const float* pr = proj + (size_t)(b * CL) * CPROJ + CDIN + c;
    float s = cb[c];
#pragma unroll
    for (int k = 0; k < 4; k++) {
        int ls = l - 3 + k;
        if (ls >= 0) s += cw[c * 4 + k] * pr[(size_t)ls * CPROJ];
    }
    xc[idx] = s / (1.f + expf(-s));
}

// ---------------- dt = softplus(raw + bias), dA = exp(-exp(A_log)*dt) ----------------
__global__ void dtprep_kernel(const float* __restrict__ proj, const float* __restrict__ dtb,
                              const float* __restrict__ alog, float* __restrict__ dt,
                              float* __restrict__ dA)
{
    int idx = blockIdx.x * blockDim.x + threadIdx.x;
    if (idx >= CBZ * CL * CNH) return;
    int h = idx & 3;
    int token = idx >> 2;
    float xv = proj[(size_t)token * CPROJ + (CDIN + CCONVD) + h] + dtb[h];
    float sp = (xv > 20.f) ? xv : log1pf(expf(xv));
    dt[idx] = sp;
    dA[idx] = expf(-expf(alog[h]) * sp);
}

// ---------------- SSM scan: 128 CTAs = (pgroup 2, head 4, batch 16), 256 thr ----------------
__global__ void __launch_bounds__(256)
scan_kernel(const float* __restrict__ xc, const float* __restrict__ dt,
            const float* __restrict__ dA, float* __restrict__ y)
{
    const int pg = blockIdx.x;   // 0..1 : p half
    const int h  = blockIdx.y;   // 0..3
    const int b  = blockIdx.z;   // 0..15
    const int tid = threadIdx.x;
    const int p_local = tid >> 3;      // 0..31
    const int noct    = tid & 7;       // 0..7
    const int nb      = noct << 4;     // n base (16 n's per thread)

    __shared__ float sBC[256];   // [0:128)=B, [128:256)=C
    __shared__ float sX[32];
    __shared__ float sDT, sDA;

    float s[16];
#pragma unroll
    for (int i = 0; i < 16; i++) s[i] = 0.f;

    const float* xcb = xc + (size_t)b * CL * CCONVD;
    const float* dtb = dt + (size_t)b * CL * CNH + h;
    const float* dAb = dA + (size_t)b * CL * CNH + h;
    float* yb = y + (size_t)b * CL * CDIN + h * CHD + pg * 32;
    const int xoff = h * CHD + pg * 32;

    // prefetch t = 0
    float rBC = xcb[CDIN + tid];
    float rX = 0.f, rDT = 0.f, rDA = 0.f;
    if (tid < 32) rX = xcb[xoff + tid];
    if (tid == 0) { rDT = dtb[0]; rDA = dAb[0]; }

    for (int t = 0; t < CL; t++) {
        // publish prefetched tile
        sBC[tid] = rBC;
        if (tid < 32) sX[tid] = rX;
        if (tid == 0) { sDT = rDT; sDA = rDA; }
        __syncthreads();
        // prefetch next tile (latency overlapped with compute below)
        int t1 = t + 1;
        if (t1 < CL) {
            const float* row = xcb + (size_t)t1 * CCONVD;
            rBC = row[CDIN + tid];
            if (tid < 32) rX = row[xoff + tid];
            if (tid == 0) { rDT = dtb[(size_t)t1 * CNH]; rDA = dAb[(size_t)t1 * CNH]; }
        }
        const float a = sDA;
        const float scale = sDT * sX[p_local];
        float acc = 0.f;
        const float4* B4 = reinterpret_cast<const float4*>(sBC + nb);
        const float4* C4 = reinterpret_cast<const float4*>(sBC + 128 + nb);
#pragma unroll
        for (int q = 0; q < 4; q++) {
            float4 bv = B4[q];
            float4 cv = C4[q];
            s[q*4+0] = a * s[q*4+0] + scale * bv.x;  acc += s[q*4+0] * cv.x;
            s[q*4+1] = a * s[q*4+1] + scale * bv.y;  acc += s[q*4+1] * cv.y;
            s[q*4+2] = a * s[q*4+2] + scale * bv.z;  acc += s[q*4+2] * cv.z;
            s[q*4+3] = a * s[q*4+3] + scale * bv.w;  acc += s[q*4+3] * cv.w;
        }
        // reduce over the 8 n-octants sharing this p (lanes differ in bits 0..2)
        acc += __shfl_xor_sync(0xffffffffu, acc, 1);
        acc += __shfl_xor_sync(0xffffffffu, acc, 2);
        acc += __shfl_xor_sync(0xffffffffu, acc, 4);
        if (noct == 0) yb[(size_t)t * CDIN + p_local] = acc;
        __syncthreads();
    }
}

// ---------------- gate (y + D*xh)*silu(z) then RMSNorm(256)*gnorm_w ----------------
__global__ void gate_norm_kernel(const float* __restrict__ y, const float* __restrict__ xc,
                                 const float* __restrict__ proj, const float* __restrict__ Dv,
                                 const float* __restrict__ gw, float* __restrict__ out)
{
    int token = blockIdx.x;            // 0..24479
    int p = threadIdx.x;               // 0..255
    float yv = y[(size_t)token * CDIN + p];
    float xh = xc[(size_t)token * CCONVD + p];
    float z  = proj[(size_t)token * CPROJ + p];
    float sz = z / (1.f + expf(-z));
    float val = (yv + Dv[p >> 6] * xh) * sz;

    __shared__ float red[8];
    __shared__ float sscale;
    float ss = val * val;
#pragma unroll
    for (int o = 16; o; o >>= 1) ss += __shfl_xor_sync(0xffffffffu, ss, o);
    if ((p & 31) == 0) red[p >> 5] = ss;
    __syncthreads();
    if (p < 32) {
        float t2 = (p < 8) ? red[p] : 0.f;
#pragma unroll
        for (int o = 4; o; o >>= 1) t2 += __shfl_xor_sync(0xffffffffu, t2, o);
        if (p == 0) sscale = rsqrtf(t2 * (1.f / 256.f) + CEPS);
    }
    __syncthreads();
    out[(size_t)token * CDIN + p] = val * sscale * gw[p];
}

// ---------------- merge fwd/bwd halves ----------------
__global__ void merge_kernel(const float* __restrict__ u, float* __restrict__ m)
{
    int idx = blockIdx.x * blockDim.x + threadIdx.x;
    if (idx >= CB0 * CL * CHID) return;
    int d = idx & 127;
    int l = (idx >> 7) % CL;
    int b = idx / (CL * CHID);
    float a = u[idx];
    float c = u[(size_t)(CB0 + b) * CL * CHID + (size_t)(CL - 1 - l) * CHID + d];
    m[idx] = 0.5f * (a + c);
}

// ---------------- un-patchify r2 output into image layout ----------------
__global__ void unpatchify(const float* __restrict__ r, float* __restrict__ out)
{
    int idx = blockIdx.x * blockDim.x + threadIdx.x;
    if (idx >= CB0 * CCIN * 340 * 720) return;
    int ww = idx % 720;
    int t  = idx / 720;
    int hh = t % 340; t /= 340;
    int c  = t % CCIN;
    int b  = t / CCIN;
    int i = hh / CPH, p = hh % CPH;
    int j = ww / CPW, q = ww % CPW;
    out[idx] = r[(size_t)(b * CL + i * CGW + j) * CPATCH + (p * CPW + q) * CCIN + c];
}

// ---------------- launcher ----------------
extern "C" void kernel_launch(void* const* d_in, const int* in_sizes, int n_in,
                              void* d_out, int out_size)
{
    const float* x        = (const float*)d_in[0];
    const float* patch_w  = (const float*)d_in[1];
    const float* patch_b  = (const float*)d_in[2];
    const float* ln_w     = (const float*)d_in[3];
    const float* in_w     = (const float*)d_in[4];
    const float* in_b     = (const float*)d_in[5];
    const float* conv_w   = (const float*)d_in[6];
    const float* conv_b   = (const float*)d_in[7];
    const float* dt_bias  = (const float*)d_in[8];
    const float* A_log    = (const float*)d_in[9];
    const float* Dw       = (const float*)d_in[10];
    const float* gnorm_w  = (const float*)d_in[11];
    const float* out_w    = (const float*)d_in[12];
    const float* out_b    = (const float*)d_in[13];
    const float* fnorm_w  = (const float*)d_in[14];
    const float* r1_w     = (const float*)d_in[15];
    const float* r1_b     = (const float*)d_in[16];
    const float* r2_w     = (const float*)d_in[17];
    const float* r2_b     = (const float*)d_in[18];

    float *h_, *u_, *proj_, *xc_, *dt_, *dA_, *y_, *g_, *m_;
    cudaGetSymbolAddress((void**)&h_,    g_h);
    cudaGetSymbolAddress((void**)&u_,    g_u);
    cudaGetSymbolAddress((void**)&proj_, g_proj);
    cudaGetSymbolAddress((void**)&xc_,   g_xc);
    cudaGetSymbolAddress((void**)&dt_,   g_dt);
    cudaGetSymbolAddress((void**)&dA_,   g_dA);
    cudaGetSymbolAddress((void**)&y_,    g_y);
    cudaGetSymbolAddress((void**)&g_,    g_g);
    cudaGetSymbolAddress((void**)&m_,    g_m);

    // 1. patch embedding
    gather_patches<<<(M_FWD * CPATCH + 255) / 256, 256>>>(x, proj_);
    gemm_kernel<0><<<dim3(2, 96), 256>>>(proj_, patch_w, patch_b, nullptr, y_,
                                         M_FWD, 127, CPATCH);
    build_h<<<(CB0 * CL * CHID + 255) / 256, 256>>>(y_, h_);

    // 2. mixer layers
    for (int layer = 0; layer < CNL; layer++) {
        rmsnorm_kernel<<<M_ALL / 8, 256>>>(h_, ln_w + layer * CHID, u_, M_ALL);
        gemm_kernel<0><<<dim3(13, 192), 256>>>(u_, in_w + (size_t)layer * CPROJ * CHID,
                                               in_b + layer * CPROJ, nullptr, proj_,
                                               M_ALL, CPROJ, CHID);
        conv_kernel<<<(CBZ * CL * CCONVD + 255) / 256, 256>>>(
            proj_, conv_w + (size_t)layer * CCONVD * 4, conv_b + layer * CCONVD, xc_);
        dtprep_kernel<<<(CBZ * CL * CNH + 255) / 256, 256>>>(
            proj_, dt_bias + layer * CNH, A_log + layer * CNH, dt_, dA_);
        scan_kernel<<<dim3(2, CNH, CBZ), 256>>>(xc_, dt_, dA_, y_);
        gate_norm_kernel<<<M_ALL, 256>>>(y_, xc_, proj_, Dw + layer * CNH,
                                         gnorm_w + layer * CDIN, g_);
        gemm_kernel<1><<<dim3(2, 192), 256>>>(g_, out_w + (size_t)layer * CHID * CDIN,
                                              out_b + layer * CHID, h_, h_,
                                              M_ALL, CHID, CDIN);
    }

    // 3. head
    rmsnorm_kernel<<<M_ALL / 8, 256>>>(h_, fnorm_w, u_, M_ALL);
    merge_kernel<<<(CB0 * CL * CHID + 255) / 256, 256>>>(u_, m_);
    gemm_kernel<2><<<dim3(2, 96), 256>>>(m_, r1_w, r1_b, nullptr, u_, M_FWD, CHID, CHID);
    gemm_kernel<0><<<dim3(8, 96), 256>>>(u_, r2_w, r2_b, nullptr, proj_, M_FWD, CPATCH, CHID);
    unpatchify<<<(CB0 * CCIN * 340 * 720 + 255) / 256, 256>>>(proj_, (float*)d_out);
}

// round 3
// speedup vs baseline: 1.1084x; 1.1084x over previous
#include <cuda_runtime.h>
#include <cuda_bf16.h>
#include <math.h>
#include <stdint.h>

// ---------------- problem constants ----------------
#define CB0   8
#define CCIN  3
#define CGH   17
#define CGW   90
#define CPH   20
#define CPW   8
#define CHID  128
#define CNL   4
#define CNH   4
#define CHD   64
#define CNST  128
#define CDIN  256      // NH*HD
#define CCONVD 512     // DIN + 2*NSTATE
#define CPROJ 772      // DIN + CONVD + NH
#define CL    1530     // GH*GW
#define CBZ   16       // 2*B0
#define CPATCH 480     // CIN*PH*PW
#define CEPS  1e-5f

#define M_FWD  (CB0*CL)    // 12240
#define M_ALL  (CBZ*CL)    // 24480

// ---------------- scratch (static device globals; no runtime alloc) ----------------
__device__ float g_h   [CBZ*CL*CHID];    // residual stream
__device__ float g_u   [CBZ*CL*CHID];    // normed / reused temp
__device__ float g_proj[CBZ*CL*CPROJ];   // in_proj out (also patch matrix & r2 out)
__device__ float g_xc  [CBZ*CL*CCONVD]; // conv+silu out
__device__ float g_dt  [CBZ*CL*CNH];
__device__ float g_dA  [CBZ*CL*CNH];
__device__ float g_y   [CBZ*CL*CDIN];    // scan out (also seq buffer)
__device__ float g_g   [CBZ*CL*CDIN];    // gated+normed
__device__ float g_m   [CB0*CL*CHID];    // merged fwd/bwd

// ---------------- tf32 helpers ----------------
__device__ __forceinline__ uint32_t f2tf32(float f) {
    uint32_t u;
    asm("cvt.rna.tf32.f32 %0, %1;" : "=r"(u) : "f"(f));
    return u;
}

__device__ __forceinline__ void mma_tf32(float* c, uint32_t a0, uint32_t a1,
                                         uint32_t a2, uint32_t a3,
                                         uint32_t b0, uint32_t b1) {
    asm volatile(
        "mma.sync.aligned.m16n8k8.row.col.f32.tf32.tf32.f32 "
        "{%0,%1,%2,%3},{%4,%5,%6,%7},{%8,%9},{%0,%1,%2,%3};"
        : "+f"(c[0]), "+f"(c[1]), "+f"(c[2]), "+f"(c[3])
        : "r"(a0), "r"(a1), "r"(a2), "r"(a3), "r"(b0), "r"(b1));
}

// ---------------- tensor-core GEMM: C[M,N] = A[M,K] @ W[N,K]^T + bias ----------------
// MODE 0: +bias;  MODE 1: +bias + residual R;  MODE 2: +bias then exact GELU
// Requires K % 32 == 0. M, N arbitrary (guarded).
// CTA tile 128x64, BK=32, 256 threads = 8 warps (2 M x 4 N), warp tile 64x16.
template<int MODE>
__global__ void __launch_bounds__(256, 2)
gemm_tc(const float* __restrict__ A, const float* __restrict__ W,
        const float* __restrict__ bias, const float* __restrict__ R,
        float* __restrict__ C, int M, int N, int K)
{
    __shared__ uint32_t As[128][36];   // [m][k], stride 36 -> conflict-free frag loads
    __shared__ uint32_t Ws[64][36];    // [n][k]

    const int tid  = threadIdx.x;
    const int warp = tid >> 5;
    const int lane = tid & 31;
    const int g    = lane >> 2;   // group id 0..7
    const int t    = lane & 3;    // thread-in-group 0..3
    const int wm   = warp >> 2;   // 0..1 -> m offset wm*64
    const int wn   = warp & 3;    // 0..3 -> n offset wn*16
    const int row0 = blockIdx.y * 128;
    const int col0 = blockIdx.x * 64;

    float acc[4][2][4];
#pragma unroll
    for (int mt = 0; mt < 4; mt++)
#pragma unroll
        for (int nt = 0; nt < 2; nt++)
#pragma unroll
            for (int j = 0; j < 4; j++) acc[mt][nt][j] = 0.f;

    const int kc = (tid & 7) << 2;   // k col within tile (0,4,...,28)
    const int rr = tid >> 3;         // row 0..31

    for (int k0 = 0; k0 < K; k0 += 32) {
        // stage A: 128 x 32, float4 loads, tf32 convert, uint4 stores
#pragma unroll
        for (int pass = 0; pass < 4; pass++) {
            int r = rr + pass * 32;
            int gr = row0 + r;
            float4 v = make_float4(0.f, 0.f, 0.f, 0.f);
            if (gr < M) v = *reinterpret_cast<const float4*>(&A[(size_t)gr * K + k0 + kc]);
            *reinterpret_cast<uint4*>(&As[r][kc]) =
                make_uint4(f2tf32(v.x), f2tf32(v.y), f2tf32(v.z), f2tf32(v.w));
        }
        // stage W: 64 x 32
#pragma unroll
        for (int pass = 0; pass < 2; pass++) {
            int r = rr + pass * 32;
            int gc = col0 + r;
            float4 v = make_float4(0.f, 0.f, 0.f, 0.f);
            if (gc < N) v = *reinterpret_cast<const float4*>(&W[(size_t)gc * K + k0 + kc]);
            *reinterpret_cast<uint4*>(&Ws[r][kc]) =
                make_uint4(f2tf32(v.x), f2tf32(v.y), f2tf32(v.z), f2tf32(v.w));
        }
        __syncthreads();

#pragma unroll
        for (int ks = 0; ks < 4; ks++) {
            const int kb = ks << 3;
            uint32_t b[2][2];
#pragma unroll
            for (int nt = 0; nt < 2; nt++) {
                int n = wn * 16 + nt * 8 + g;
                b[nt][0] = Ws[n][kb + t];
                b[nt][1] = Ws[n][kb + t + 4];
            }
#pragma unroll
            for (int mt = 0; mt < 4; mt++) {
                int m = wm * 64 + mt * 16;
                uint32_t a0 = As[m + g][kb + t];
                uint32_t a1 = As[m + g + 8][kb + t];
                uint32_t a2 = As[m + g][kb + t + 4];
                uint32_t a3 = As[m + g + 8][kb + t + 4];
#pragma unroll
                for (int nt = 0; nt < 2; nt++)
                    mma_tf32(acc[mt][nt], a0, a1, a2, a3, b[nt][0], b[nt][1]);
            }
        }
        __syncthreads();
    }

    // epilogue
#pragma unroll
    for (int mt = 0; mt < 4; mt++) {
        int rl = row0 + wm * 64 + mt * 16 + g;
#pragma unroll
        for (int half = 0; half < 2; half++) {
            int r = rl + half * 8;
            if (r >= M) continue;
#pragma unroll
            for (int nt = 0; nt < 2; nt++) {
                int cb = col0 + wn * 16 + nt * 8 + 2 * t;
#pragma unroll
                for (int j = 0; j < 2; j++) {
                    int c = cb + j;
                    if (c >= N) continue;
                    float v = acc[mt][nt][half * 2 + j] + bias[c];
                    if (MODE == 1) v += R[(size_t)r * N + c];
                    if (MODE == 2) v = 0.5f * v * (1.f + erff(v * 0.70710678118654752f));
                    C[(size_t)r * N + c] = v;
                }
            }
        }
    }
}

// ---------------- patch gather: Apat[12240][480] ----------------
__global__ void gather_patches(const float* __restrict__ x, float* __restrict__ Apat)
{
    int idx = blockIdx.x * blockDim.x + threadIdx.x;
    if (idx >= M_FWD * CPATCH) return;
    int col = idx % CPATCH;
    int row = idx / CPATCH;
    int c = col / 160, rem = col % 160;
    int p = rem >> 3, q = rem & 7;
    int b = row / CL, l = row % CL;
    int i = l / CGW, j = l % CGW;
    Apat[idx] = x[(((size_t)b * CCIN + c) * 340 + (i * CPH + p)) * 720 + (j * CPW + q)];
}

// ---------------- build h: seq + gain channel, forward + reversed ----------------
__global__ void build_h(const float* __restrict__ seq /*12240 x 127*/, float* __restrict__ h)
{
    int idx = blockIdx.x * blockDim.x + threadIdx.x;
    if (idx >= CB0 * CL * CHID) return;
    int d = idx & 127;
    int l = (idx >> 7) % CL;
    int b = idx / (CL * CHID);
    float v;
    if (d < 127) v = seq[(size_t)(b * CL + l) * 127 + d];
    else         v = (float)(l / CGW) * (1.f / 16.f);
    h[idx] = v;
    h[(size_t)(CB0 + b) * CL * CHID + (size_t)(CL - 1 - l) * CHID + d] = v;
}

// ---------------- RMSNorm over 128 (warp per row) ----------------
__global__ void rmsnorm_kernel(const float* __restrict__ in, const float* __restrict__ w,
                               float* __restrict__ out, int rows)
{
    int warp = blockIdx.x * (blockDim.x >> 5) + (threadIdx.x >> 5);
    if (warp >= rows) return;
    int lane = threadIdx.x & 31;
    float4 v = reinterpret_cast<const float4*>(in + (size_t)warp * CHID)[lane];
    float ss = v.x * v.x + v.y * v.y + v.z * v.z + v.w * v.w;
#pragma unroll
    for (int o = 16; o; o >>= 1) ss += __shfl_xor_sync(0xffffffffu, ss, o);
    float sc = rsqrtf(ss * (1.f / 128.f) + CEPS);
    float4 wv = reinterpret_cast<const float4*>(w)[lane];
    float4 ov = make_float4(v.x * sc * wv.x, v.y * sc * wv.y, v.z * sc * wv.z, v.w * sc * wv.w);
    reinterpret_cast<float4*>(out + (size_t)warp * CHID)[lane] = ov;
}

// ---------------- depthwise causal conv(K=4) + SiLU ----------------
__global__ void conv_kernel(const float* __restrict__ proj, const float* __restrict__ cw,
                            const float* __restrict__ cb, float* __restrict__ xc)
{
    int idx = blockIdx.x * blockDim.x + threadIdx.x;
    if (idx >= CBZ * CL * CCONVD) return;
    int c = idx & (CCONVD - 1);
    int l = (idx >> 9) % CL;
    int b = idx / (CL * CCONVD);
    const float* pr = proj + (size_t)(b * CL) * CPROJ + CDIN + c;
    float s = cb[c];
#pragma unroll
    for (int k = 0; k < 4; k++) {
        int ls = l - 3 + k;
        if (ls >= 0) s += cw[c * 4 + k] * pr[(size_t)ls * CPROJ];
    }
    xc[idx] = s / (1.f + expf(-s));
}

// ---------------- dt = softplus(raw + bias), dA = exp(-exp(A_log)*dt) ----------------
__global__ void dtprep_kernel(const float* __restrict__ proj, const float* __restrict__ dtb,
                              const float* __restrict__ alog, float* __restrict__ dt,
                              float* __restrict__ dA)
{
    int idx = blockIdx.x * blockDim.x + threadIdx.x;
    if (idx >= CBZ * CL * CNH) return;
    int h = idx & 3;
    int token = idx >> 2;
    float xv = proj[(size_t)token * CPROJ + (CDIN + CCONVD) + h] + dtb[h];
    float sp = (xv > 20.f) ? xv : log1pf(expf(xv));
    dt[idx] = sp;
    dA[idx] = expf(-expf(alog[h]) * sp);
}

// ---------------- SSM scan: 128 CTAs = (pgroup 2, head 4, batch 16), 256 thr ----------------
__global__ void __launch_bounds__(256)
scan_kernel(const float* __restrict__ xc, const float* __restrict__ dt,
            const float* __restrict__ dA, float* __restrict__ y)
{
    const int pg = blockIdx.x;   // 0..1 : p half
    const int h  = blockIdx.y;   // 0..3
    const int b  = blockIdx.z;   // 0..15
    const int tid = threadIdx.x;
    const int p_local = tid >> 3;      // 0..31
    const int noct    = tid & 7;       // 0..7
    const int nb      = noct << 4;     // n base (16 n's per thread)

    __shared__ float sBC[256];   // [0:128)=B, [128:256)=C
    __shared__ float sX[32];
    __shared__ float sDT, sDA;

    float s[16];
#pragma unroll
    for (int i = 0; i < 16; i++) s[i] = 0.f;

    const float* xcb = xc + (size_t)b * CL * CCONVD;
    const float* dtb = dt + (size_t)b * CL * CNH + h;
    const float* dAb = dA + (size_t)b * CL * CNH + h;
    float* yb = y + (size_t)b * CL * CDIN + h * CHD + pg * 32;
    const int xoff = h * CHD + pg * 32;

    // prefetch t = 0
    float rBC = xcb[CDIN + tid];
    float rX = 0.f, rDT = 0.f, rDA = 0.f;
    if (tid < 32) rX = xcb[xoff + tid];
    if (tid == 0) { rDT = dtb[0]; rDA = dAb[0]; }

    for (int t = 0; t < CL; t++) {
        // publish prefetched tile
        sBC[tid] = rBC;
        if (tid < 32) sX[tid] = rX;
        if (tid == 0) { sDT = rDT; sDA = rDA; }
        __syncthreads();
        // prefetch next tile (latency overlapped with compute below)
        int t1 = t + 1;
        if (t1 < CL) {
            const float* row = xcb + (size_t)t1 * CCONVD;
            rBC = row[CDIN + tid];
            if (tid < 32) rX = row[xoff + tid];
            if (tid == 0) { rDT = dtb[(size_t)t1 * CNH]; rDA = dAb[(size_t)t1 * CNH]; }
        }
        const float a = sDA;
        const float scale = sDT * sX[p_local];
        float acc = 0.f;
        const float4* B4 = reinterpret_cast<const float4*>(sBC + nb);
        const float4* C4 = reinterpret_cast<const float4*>(sBC + 128 + nb);
#pragma unroll
        for (int q = 0; q < 4; q++) {
            float4 bv = B4[q];
            float4 cv = C4[q];
            s[q*4+0] = a * s[q*4+0] + scale * bv.x;  acc += s[q*4+0] * cv.x;
            s[q*4+1] = a * s[q*4+1] + scale * bv.y;  acc += s[q*4+1] * cv.y;
            s[q*4+2] = a * s[q*4+2] + scale * bv.z;  acc += s[q*4+2] * cv.z;
            s[q*4+3] = a * s[q*4+3] + scale * bv.w;  acc += s[q*4+3] * cv.w;
        }
        // reduce over the 8 n-octants sharing this p (lanes differ in bits 0..2)
        acc += __shfl_xor_sync(0xffffffffu, acc, 1);
        acc += __shfl_xor_sync(0xffffffffu, acc, 2);
        acc += __shfl_xor_sync(0xffffffffu, acc, 4);
        if (noct == 0) yb[(size_t)t * CDIN + p_local] = acc;
        __syncthreads();
    }
}

// ---------------- gate (y + D*xh)*silu(z) then RMSNorm(256)*gnorm_w ----------------
__global__ void gate_norm_kernel(const float* __restrict__ y, const float* __restrict__ xc,
                                 const float* __restrict__ proj, const float* __restrict__ Dv,
                                 const float* __restrict__ gw, float* __restrict__ out)
{
    int token = blockIdx.x;            // 0..24479
    int p = threadIdx.x;               // 0..255
    float yv = y[(size_t)token * CDIN + p];
    float xh = xc[(size_t)token * CCONVD + p];
    float z  = proj[(size_t)token * CPROJ + p];
    float sz = z / (1.f + expf(-z));
    float val = (yv + Dv[p >> 6] * xh) * sz;

    __shared__ float red[8];
    __shared__ float sscale;
    float ss = val * val;
#pragma unroll
    for (int o = 16; o; o >>= 1) ss += __shfl_xor_sync(0xffffffffu, ss, o);
    if ((p & 31) == 0) red[p >> 5] = ss;
    __syncthreads();
    if (p < 32) {
        float t2 = (p < 8) ? red[p] : 0.f;
#pragma unroll
        for (int o = 4; o; o >>= 1) t2 += __shfl_xor_sync(0xffffffffu, t2, o);
        if (p == 0) sscale = rsqrtf(t2 * (1.f / 256.f) + CEPS);
    }
    __syncthreads();
    out[(size_t)token * CDIN + p] = val * sscale * gw[p];
}

// ---------------- merge fwd/bwd halves ----------------
__global__ void merge_kernel(const float* __restrict__ u, float* __restrict__ m)
{
    int idx = blockIdx.x * blockDim.x + threadIdx.x;
    if (idx >= CB0 * CL * CHID) return;
    int d = idx & 127;
    int l = (idx >> 7) % CL;
    int b = idx / (CL * CHID);
    float a = u[idx];
    float c = u[(size_t)(CB0 + b) * CL * CHID + (size_t)(CL - 1 - l) * CHID + d];
    m[idx] = 0.5f * (a + c);
}

// ---------------- un-patchify r2 output into image layout ----------------
__global__ void unpatchify(const float* __restrict__ r, float* __restrict__ out)
{
    int idx = blockIdx.x * blockDim.x + threadIdx.x;
    if (idx >= CB0 * CCIN * 340 * 720) return;
    int ww = idx % 720;
    int t  = idx / 720;
    int hh = t % 340; t /= 340;
    int c  = t % CCIN;
    int b  = t / CCIN;
    int i = hh / CPH, p = hh % CPH;
    int j = ww / CPW, q = ww % CPW;
    out[idx] = r[(size_t)(b * CL + i * CGW + j) * CPATCH + (p * CPW + q) * CCIN + c];
}

// ---------------- launcher ----------------
extern "C" void kernel_launch(void* const* d_in, const int* in_sizes, int n_in,
                              void* d_out, int out_size)
{
    const float* x        = (const float*)d_in[0];
    const float* patch_w  = (const float*)d_in[1];
    const float* patch_b  = (const float*)d_in[2];
    const float* ln_w     = (const float*)d_in[3];
    const float* in_w     = (const float*)d_in[4];
    const float* in_b     = (const float*)d_in[5];
    const float* conv_w   = (const float*)d_in[6];
    const float* conv_b   = (const float*)d_in[7];
    const float* dt_bias  = (const float*)d_in[8];
    const float* A_log    = (const float*)d_in[9];
    const float* Dw       = (const float*)d_in[10];
    const float* gnorm_w  = (const float*)d_in[11];
    const float* out_w    = (const float*)d_in[12];
    const float* out_b    = (const float*)d_in[13];
    const float* fnorm_w  = (const float*)d_in[14];
    const float* r1_w     = (const float*)d_in[15];
    const float* r1_b     = (const float*)d_in[16];
    const float* r2_w     = (const float*)d_in[17];
    const float* r2_b     = (const float*)d_in[18];

    float *h_, *u_, *proj_, *xc_, *dt_, *dA_, *y_, *g_, *m_;
    cudaGetSymbolAddress((void**)&h_,    g_h);
    cudaGetSymbolAddress((void**)&u_,    g_u);
    cudaGetSymbolAddress((void**)&proj_, g_proj);
    cudaGetSymbolAddress((void**)&xc_,   g_xc);
    cudaGetSymbolAddress((void**)&dt_,   g_dt);
    cudaGetSymbolAddress((void**)&dA_,   g_dA);
    cudaGetSymbolAddress((void**)&y_,    g_y);
    cudaGetSymbolAddress((void**)&g_,    g_g);
    cudaGetSymbolAddress((void**)&m_,    g_m);

    // 1. patch embedding
    gather_patches<<<(M_FWD * CPATCH + 255) / 256, 256>>>(x, proj_);
    gemm_tc<0><<<dim3(2, 96), 256>>>(proj_, patch_w, patch_b, nullptr, y_,
                                     M_FWD, 127, CPATCH);
    build_h<<<(CB0 * CL * CHID + 255) / 256, 256>>>(y_, h_);

    // 2. mixer layers
    for (int layer = 0; layer < CNL; layer++) {
        rmsnorm_kernel<<<M_ALL / 8, 256>>>(h_, ln_w + layer * CHID, u_, M_ALL);
        gemm_tc<0><<<dim3(13, 192), 256>>>(u_, in_w + (size_t)layer * CPROJ * CHID,
                                           in_b + layer * CPROJ, nullptr, proj_,
                                           M_ALL, CPROJ, CHID);
        conv_kernel<<<(CBZ * CL * CCONVD + 255) / 256, 256>>>(
            proj_, conv_w + (size_t)layer * CCONVD * 4, conv_b + layer * CCONVD, xc_);
        dtprep_kernel<<<(CBZ * CL * CNH + 255) / 256, 256>>>(
            proj_, dt_bias + layer * CNH, A_log + layer * CNH, dt_, dA_);
        scan_kernel<<<dim3(2, CNH, CBZ), 256>>>(xc_, dt_, dA_, y_);
        gate_norm_kernel<<<M_ALL, 256>>>(y_, xc_, proj_, Dw + layer * CNH,
                                         gnorm_w + layer * CDIN, g_);
        gemm_tc<1><<<dim3(2, 192), 256>>>(g_, out_w + (size_t)layer * CHID * CDIN,
                                          out_b + layer * CHID, h_, h_,
                                          M_ALL, CHID, CDIN);
    }

    // 3. head
    rmsnorm_kernel<<<M_ALL / 8, 256>>>(h_, fnorm_w, u_, M_ALL);
    merge_kernel<<<(CB0 * CL * CHID + 255) / 256, 256>>>(u_, m_);
    gemm_tc<2><<<dim3(2, 96), 256>>>(m_, r1_w, r1_b, nullptr, u_, M_FWD, CHID, CHID);
    gemm_tc<0><<<dim3(8, 96), 256>>>(u_, r2_w, r2_b, nullptr, proj_, M_FWD, CPATCH, CHID);
    unpatchify<<<(CB0 * CCIN * 340 * 720 + 255) / 256, 256>>>(proj_, (float*)d_out);
}

// round 4
// speedup vs baseline: 2.8576x; 2.5782x over previous
#include <cuda_runtime.h>
#include <cuda_bf16.h>
#include <math.h>
#include <stdint.h>

// ---------------- problem constants ----------------
#define CB0   8
#define CCIN  3
#define CGH   17
#define CGW   90
#define CPH   20
#define CPW   8
#define CHID  128
#define CNL   4
#define CNH   4
#define CHD   64
#define CNST  128
#define CDIN  256      // NH*HD
#define CCONVD 512     // DIN + 2*NSTATE
#define CPROJ 772      // DIN + CONVD + NH
#define CL    1530     // GH*GW
#define CBZ   16       // 2*B0
#define CPATCH 480     // CIN*PH*PW
#define CEPS  1e-5f

#define M_FWD  (CB0*CL)    // 12240
#define M_ALL  (CBZ*CL)    // 24480

#define SCHUNK 18
#define SNCH   (CL / SCHUNK)   // 85 exactly

// ---------------- scratch (static device globals; no runtime alloc) ----------------
__device__ float g_h   [CBZ*CL*CHID];    // residual stream
__device__ float g_u   [CBZ*CL*CHID];    // normed / reused temp
__device__ float g_proj[CBZ*CL*CPROJ];   // in_proj out (also patch matrix & r2 out)
__device__ float g_xc  [CBZ*CL*CCONVD]; // conv+silu out
__device__ float g_dt  [CBZ*CL*CNH];
__device__ float g_dA  [CBZ*CL*CNH];
__device__ float g_y   [CBZ*CL*CDIN];    // scan out (also seq buffer)
__device__ float g_g   [CBZ*CL*CDIN];    // gated+normed
__device__ float g_m   [CB0*CL*CHID];    // merged fwd/bwd

// ---------------- tf32 helpers ----------------
__device__ __forceinline__ uint32_t f2tf32(float f) {
    uint32_t u;
    asm("cvt.rna.tf32.f32 %0, %1;" : "=r"(u) : "f"(f));
    return u;
}

__device__ __forceinline__ void mma_tf32(float* c, uint32_t a0, uint32_t a1,
                                         uint32_t a2, uint32_t a3,
                                         uint32_t b0, uint32_t b1) {
    asm volatile(
        "mma.sync.aligned.m16n8k8.row.col.f32.tf32.tf32.f32 "
        "{%0,%1,%2,%3},{%4,%5,%6,%7},{%8,%9},{%0,%1,%2,%3};"
        : "+f"(c[0]), "+f"(c[1]), "+f"(c[2]), "+f"(c[3])
        : "r"(a0), "r"(a1), "r"(a2), "r"(a3), "r"(b0), "r"(b1));
}

// ---------------- tensor-core GEMM: C[M,N] = A[M,K] @ W[N,K]^T + bias ----------------
// MODE 0: +bias;  MODE 1: +bias + residual R;  MODE 2: +bias then exact GELU
template<int MODE>
__global__ void __launch_bounds__(256, 2)
gemm_tc(const float* __restrict__ A, const float* __restrict__ W,
        const float* __restrict__ bias, const float* __restrict__ R,
        float* __restrict__ C, int M, int N, int K)
{
    __shared__ uint32_t As[128][36];   // [m][k], stride 36 -> conflict-free frag loads
    __shared__ uint32_t Ws[64][36];    // [n][k]

    const int tid  = threadIdx.x;
    const int warp = tid >> 5;
    const int lane = tid & 31;
    const int g    = lane >> 2;   // group id 0..7
    const int t    = lane & 3;    // thread-in-group 0..3
    const int wm   = warp >> 2;   // 0..1 -> m offset wm*64
    const int wn   = warp & 3;    // 0..3 -> n offset wn*16
    const int row0 = blockIdx.y * 128;
    const int col0 = blockIdx.x * 64;

    float acc[4][2][4];
#pragma unroll
    for (int mt = 0; mt < 4; mt++)
#pragma unroll
        for (int nt = 0; nt < 2; nt++)
#pragma unroll
            for (int j = 0; j < 4; j++) acc[mt][nt][j] = 0.f;

    const int kc = (tid & 7) << 2;   // k col within tile (0,4,...,28)
    const int rr = tid >> 3;         // row 0..31

    for (int k0 = 0; k0 < K; k0 += 32) {
#pragma unroll
        for (int pass = 0; pass < 4; pass++) {
            int r = rr + pass * 32;
            int gr = row0 + r;
            float4 v = make_float4(0.f, 0.f, 0.f, 0.f);
            if (gr < M) v = *reinterpret_cast<const float4*>(&A[(size_t)gr * K + k0 + kc]);
            *reinterpret_cast<uint4*>(&As[r][kc]) =
                make_uint4(f2tf32(v.x), f2tf32(v.y), f2tf32(v.z), f2tf32(v.w));
        }
#pragma unroll
        for (int pass = 0; pass < 2; pass++) {
            int r = rr + pass * 32;
            int gc = col0 + r;
            float4 v = make_float4(0.f, 0.f, 0.f, 0.f);
            if (gc < N) v = *reinterpret_cast<const float4*>(&W[(size_t)gc * K + k0 + kc]);
            *reinterpret_cast<uint4*>(&Ws[r][kc]) =
                make_uint4(f2tf32(v.x), f2tf32(v.y), f2tf32(v.z), f2tf32(v.w));
        }
        __syncthreads();

#pragma unroll
        for (int ks = 0; ks < 4; ks++) {
            const int kb = ks << 3;
            uint32_t b[2][2];
#pragma unroll
            for (int nt = 0; nt < 2; nt++) {
                int n = wn * 16 + nt * 8 + g;
                b[nt][0] = Ws[n][kb + t];
                b[nt][1] = Ws[n][kb + t + 4];
            }
#pragma unroll
            for (int mt = 0; mt < 4; mt++) {
                int m = wm * 64 + mt * 16;
                uint32_t a0 = As[m + g][kb + t];
                uint32_t a1 = As[m + g + 8][kb + t];
                uint32_t a2 = As[m + g][kb + t + 4];
                uint32_t a3 = As[m + g + 8][kb + t + 4];
#pragma unroll
                for (int nt = 0; nt < 2; nt++)
                    mma_tf32(acc[mt][nt], a0, a1, a2, a3, b[nt][0], b[nt][1]);
            }
        }
        __syncthreads();
    }

#pragma unroll
    for (int mt = 0; mt < 4; mt++) {
        int rl = row0 + wm * 64 + mt * 16 + g;
#pragma unroll
        for (int half = 0; half < 2; half++) {
            int r = rl + half * 8;
            if (r >= M) continue;
#pragma unroll
            for (int nt = 0; nt < 2; nt++) {
                int cb = col0 + wn * 16 + nt * 8 + 2 * t;
#pragma unroll
                for (int j = 0; j < 2; j++) {
                    int c = cb + j;
                    if (c >= N) continue;
                    float v = acc[mt][nt][half * 2 + j] + bias[c];
                    if (MODE == 1) v += R[(size_t)r * N + c];
                    if (MODE == 2) v = 0.5f * v * (1.f + erff(v * 0.70710678118654752f));
                    C[(size_t)r * N + c] = v;
                }
            }
        }
    }
}

// ---------------- patch gather: Apat[12240][480] ----------------
__global__ void gather_patches(const float* __restrict__ x, float* __restrict__ Apat)
{
    int idx = blockIdx.x * blockDim.x + threadIdx.x;
    if (idx >= M_FWD * CPATCH) return;
    int col = idx % CPATCH;
    int row = idx / CPATCH;
    int c = col / 160, rem = col % 160;
    int p = rem >> 3, q = rem & 7;
    int b = row / CL, l = row % CL;
    int i = l / CGW, j = l % CGW;
    Apat[idx] = x[(((size_t)b * CCIN + c) * 340 + (i * CPH + p)) * 720 + (j * CPW + q)];
}

// ---------------- build h: seq + gain channel, forward + reversed ----------------
__global__ void build_h(const float* __restrict__ seq /*12240 x 127*/, float* __restrict__ h)
{
    int idx = blockIdx.x * blockDim.x + threadIdx.x;
    if (idx >= CB0 * CL * CHID) return;
    int d = idx & 127;
    int l = (idx >> 7) % CL;
    int b = idx / (CL * CHID);
    float v;
    if (d < 127) v = seq[(size_t)(b * CL + l) * 127 + d];
    else         v = (float)(l / CGW) * (1.f / 16.f);
    h[idx] = v;
    h[(size_t)(CB0 + b) * CL * CHID + (size_t)(CL - 1 - l) * CHID + d] = v;
}

// ---------------- RMSNorm over 128 (warp per row) ----------------
__global__ void rmsnorm_kernel(const float* __restrict__ in, const float* __restrict__ w,
                               float* __restrict__ out, int rows)
{
    int warp = blockIdx.x * (blockDim.x >> 5) + (threadIdx.x >> 5);
    if (warp >= rows) return;
    int lane = threadIdx.x & 31;
    float4 v = reinterpret_cast<const float4*>(in + (size_t)warp * CHID)[lane];
    float ss = v.x * v.x + v.y * v.y + v.z * v.z + v.w * v.w;
#pragma unroll
    for (int o = 16; o; o >>= 1) ss += __shfl_xor_sync(0xffffffffu, ss, o);
    float sc = rsqrtf(ss * (1.f / 128.f) + CEPS);
    float4 wv = reinterpret_cast<const float4*>(w)[lane];
    float4 ov = make_float4(v.x * sc * wv.x, v.y * sc * wv.y, v.z * sc * wv.z, v.w * sc * wv.w);
    reinterpret_cast<float4*>(out + (size_t)warp * CHID)[lane] = ov;
}

// ---------------- depthwise causal conv(K=4) + SiLU ----------------
__global__ void conv_kernel(const float* __restrict__ proj, const float* __restrict__ cw,
                            const float* __restrict__ cb, float* __restrict__ xc)
{
    int idx = blockIdx.x * blockDim.x + threadIdx.x;
    if (idx >= CBZ * CL * CCONVD) return;
    int c = idx & (CCONVD - 1);
    int l = (idx >> 9) % CL;
    int b = idx / (CL * CCONVD);
    const float* pr = proj + (size_t)(b * CL) * CPROJ + CDIN + c;
    float s = cb[c];
#pragma unroll
    for (int k = 0; k < 4; k++) {
        int ls = l - 3 + k;
        if (ls >= 0) s += cw[c * 4 + k] * pr[(size_t)ls * CPROJ];
    }
    xc[idx] = s / (1.f + __expf(-s));
}

// ---------------- dt = softplus(raw + bias), dA = exp(-exp(A_log)*dt) ----------------
__global__ void dtprep_kernel(const float* __restrict__ proj, const float* __restrict__ dtb,
                              const float* __restrict__ alog, float* __restrict__ dt,
                              float* __restrict__ dA)
{
    int idx = blockIdx.x * blockDim.x + threadIdx.x;
    if (idx >= CBZ * CL * CNH) return;
    int h = idx & 3;
    int token = idx >> 2;
    float xv = proj[(size_t)token * CPROJ + (CDIN + CCONVD) + h] + dtb[h];
    float sp = (xv > 20.f) ? xv : log1pf(__expf(xv));
    dt[idx] = sp;
    dA[idx] = __expf(-__expf(alog[h]) * sp);
}

// ---------------- SSM scan v2: chunked cp.async staging, conflict-free SMEM ----------------
// grid (2, 4, 16) = (pgroup, head, batch), 256 threads.
// Per chunk of 18 timesteps: stage B/C (padded stride-36 layout), x-slice, dt, dA via
// cp.async into double-buffered SMEM; ONE __syncthreads per chunk.
__global__ void __launch_bounds__(256)
scan_kernel(const float* __restrict__ xc, const float* __restrict__ dt,
            const float* __restrict__ dA, float* __restrict__ y)
{
    const int pg = blockIdx.x;
    const int h  = blockIdx.y;
    const int b  = blockIdx.z;
    const int tid = threadIdx.x;
    const int p_local = tid >> 3;      // 0..31
    const int noct    = tid & 7;       // 0..7
    const int nb      = noct << 4;     // n base (16 n's per thread)

    __shared__ __align__(16) float sBC[2][SCHUNK][288];  // BC idx m -> (m>>5)*36 + (m&31)
    __shared__ __align__(16) float sX [2][SCHUNK][32];
    __shared__ float sDT[2][SCHUNK];
    __shared__ float sDA[2][SCHUNK];

    const float* xcb = xc + (size_t)b * CL * CCONVD;
    const float* dtb = dt + ((size_t)b * CL) * CNH + h;
    const float* dAb = dA + ((size_t)b * CL) * CNH + h;
    float* yb = y + (size_t)b * CL * CDIN + h * CHD + pg * 32;
    const int xoff = h * CHD + pg * 32;

    float s[16];
#pragma unroll
    for (int i = 0; i < 16; i++) s[i] = 0.f;

    // padded offsets for this thread's B/C float4 groups (B at m=nb.., C at m=128+nb..)
    const int gB = ((nb >> 5) * 36) + (nb & 31);
    const int gC = (((nb + 128) >> 5) * 36) + ((nb + 128) & 31);

#define SCAN_ISSUE(cc)                                                              \
    {                                                                               \
        const int buf_ = (cc) & 1;                                                  \
        const int t0_  = (cc) * SCHUNK;                                             \
        for (int i = tid; i < SCHUNK * 64; i += 256) {                              \
            int tt = i >> 6, n0 = (i & 63) << 2;                                    \
            int doff = ((n0 >> 5) * 36) + (n0 & 31);                                \
            uint32_t da = (uint32_t)__cvta_generic_to_shared(&sBC[buf_][tt][doff]); \
            const float* src = xcb + (size_t)(t0_ + tt) * CCONVD + CDIN + n0;       \
            asm volatile("cp.async.ca.shared.global [%0], [%1], 16;" :: "r"(da), "l"(src)); \
        }                                                                           \
        for (int i = tid; i < SCHUNK * 8; i += 256) {                               \
            int tt = i >> 3, n0 = (i & 7) << 2;                                     \
            uint32_t da = (uint32_t)__cvta_generic_to_shared(&sX[buf_][tt][n0]);    \
            const float* src = xcb + (size_t)(t0_ + tt) * CCONVD + xoff + n0;       \
            asm volatile("cp.async.ca.shared.global [%0], [%1], 16;" :: "r"(da), "l"(src)); \
        }                                                                           \
        if (tid < SCHUNK) {                                                         \
            uint32_t da = (uint32_t)__cvta_generic_to_shared(&sDT[buf_][tid]);      \
            const float* src = dtb + (size_t)(t0_ + tid) * CNH;                     \
            asm volatile("cp.async.ca.shared.global [%0], [%1], 4;" :: "r"(da), "l"(src)); \
            uint32_t da2 = (uint32_t)__cvta_generic_to_shared(&sDA[buf_][tid]);     \
            const float* src2 = dAb + (size_t)(t0_ + tid) * CNH;                    \
            asm volatile("cp.async.ca.shared.global [%0], [%1], 4;" :: "r"(da2), "l"(src2)); \
        }                                                                           \
        asm volatile("cp.async.commit_group;");                                     \
    }

    SCAN_ISSUE(0);

    for (int c = 0; c < SNCH; c++) {
        asm volatile("cp.async.wait_group 0;");
        __syncthreads();
        if (c + 1 < SNCH) SCAN_ISSUE(c + 1);
        const int buf = c & 1;
        const int t0 = c * SCHUNK;
#pragma unroll 6
        for (int tt = 0; tt < SCHUNK; tt++) {
            const float a = sDA[buf][tt];
            const float scale = sDT[buf][tt] * sX[buf][tt][p_local];
            const float* base = &sBC[buf][tt][0];
            float acc = 0.f;
#pragma unroll
            for (int q = 0; q < 4; q++) {
                float4 bv = *reinterpret_cast<const float4*>(base + gB + 4 * q);
                float4 cv = *reinterpret_cast<const float4*>(base + gC + 4 * q);
                s[q*4+0] = a * s[q*4+0] + scale * bv.x;  acc += s[q*4+0] * cv.x;
                s[q*4+1] = a * s[q*4+1] + scale * bv.y;  acc += s[q*4+1] * cv.y;
                s[q*4+2] = a * s[q*4+2] + scale * bv.z;  acc += s[q*4+2] * cv.z;
                s[q*4+3] = a * s[q*4+3] + scale * bv.w;  acc += s[q*4+3] * cv.w;
            }
            acc += __shfl_xor_sync(0xffffffffu, acc, 1);
            acc += __shfl_xor_sync(0xffffffffu, acc, 2);
            acc += __shfl_xor_sync(0xffffffffu, acc, 4);
            if (noct == 0) yb[(size_t)(t0 + tt) * CDIN + p_local] = acc;
        }
    }
#undef SCAN_ISSUE
}

// ---------------- gate (y + D*xh)*silu(z) then RMSNorm(256)*gnorm_w ----------------
__global__ void gate_norm_kernel(const float* __restrict__ y, const float* __restrict__ xc,
                                 const float* __restrict__ proj, const float* __restrict__ Dv,
                                 const float* __restrict__ gw, float* __restrict__ out)
{
    int token = blockIdx.x;            // 0..24479
    int p = threadIdx.x;               // 0..255
    float yv = y[(size_t)token * CDIN + p];
    float xh = xc[(size_t)token * CCONVD + p];
    float z  = proj[(size_t)token * CPROJ + p];
    float sz = z / (1.f + __expf(-z));
    float val = (yv + Dv[p >> 6] * xh) * sz;

    __shared__ float red[8];
    __shared__ float sscale;
    float ss = val * val;
#pragma unroll
    for (int o = 16; o; o >>= 1) ss += __shfl_xor_sync(0xffffffffu, ss, o);
    if ((p & 31) == 0) red[p >> 5] = ss;
    __syncthreads();
    if (p < 32) {
        float t2 = (p < 8) ? red[p] : 0.f;
#pragma unroll
        for (int o = 4; o; o >>= 1) t2 += __shfl_xor_sync(0xffffffffu, t2, o);
        if (p == 0) sscale = rsqrtf(t2 * (1.f / 256.f) + CEPS);
    }
    __syncthreads();
    out[(size_t)token * CDIN + p] = val * sscale * gw[p];
}

// ---------------- merge fwd/bwd halves ----------------
__global__ void merge_kernel(const float* __restrict__ u, float* __restrict__ m)
{
    int idx = blockIdx.x * blockDim.x + threadIdx.x;
    if (idx >= CB0 * CL * CHID) return;
    int d = idx & 127;
    int l = (idx >> 7) % CL;
    int b = idx / (CL * CHID);
    float a = u[idx];
    float c = u[(size_t)(CB0 + b) * CL * CHID + (size_t)(CL - 1 - l) * CHID + d];
    m[idx] = 0.5f * (a + c);
}

// ---------------- un-patchify r2 output into image layout ----------------
__global__ void unpatchify(const float* __restrict__ r, float* __restrict__ out)
{
    int idx = blockIdx.x * blockDim.x + threadIdx.x;
    if (idx >= CB0 * CCIN * 340 * 720) return;
    int ww = idx % 720;
    int t  = idx / 720;
    int hh = t % 340; t /= 340;
    int c  = t % CCIN;
    int b  = t / CCIN;
    int i = hh / CPH, p = hh % CPH;
    int j = ww / CPW, q = ww % CPW;
    out[idx] = r[(size_t)(b * CL + i * CGW + j) * CPATCH + (p * CPW + q) * CCIN + c];
}

// ---------------- launcher ----------------
extern "C" void kernel_launch(void* const* d_in, const int* in_sizes, int n_in,
                              void* d_out, int out_size)
{
    const float* x        = (const float*)d_in[0];
    const float* patch_w  = (const float*)d_in[1];
    const float* patch_b  = (const float*)d_in[2];
    const float* ln_w     = (const float*)d_in[3];
    const float* in_w     = (const float*)d_in[4];
    const float* in_b     = (const float*)d_in[5];
    const float* conv_w   = (const float*)d_in[6];
    const float* conv_b   = (const float*)d_in[7];
    const float* dt_bias  = (const float*)d_in[8];
    const float* A_log    = (const float*)d_in[9];
    const float* Dw       = (const float*)d_in[10];
    const float* gnorm_w  = (const float*)d_in[11];
    const float* out_w    = (const float*)d_in[12];
    const float* out_b    = (const float*)d_in[13];
    const float* fnorm_w  = (const float*)d_in[14];
    const float* r1_w     = (const float*)d_in[15];
    const float* r1_b     = (const float*)d_in[16];
    const float* r2_w     = (const float*)d_in[17];
    const float* r2_b     = (const float*)d_in[18];

    float *h_, *u_, *proj_, *xc_, *dt_, *dA_, *y_, *g_, *m_;
    cudaGetSymbolAddress((void**)&h_,    g_h);
    cudaGetSymbolAddress((void**)&u_,    g_u);
    cudaGetSymbolAddress((void**)&proj_, g_proj);
    cudaGetSymbolAddress((void**)&xc_,   g_xc);
    cudaGetSymbolAddress((void**)&dt_,   g_dt);
    cudaGetSymbolAddress((void**)&dA_,   g_dA);
    cudaGetSymbolAddress((void**)&y_,    g_y);
    cudaGetSymbolAddress((void**)&g_,    g_g);
    cudaGetSymbolAddress((void**)&m_,    g_m);

    // 1. patch embedding
    gather_patches<<<(M_FWD * CPATCH + 255) / 256, 256>>>(x, proj_);
    gemm_tc<0><<<dim3(2, 96), 256>>>(proj_, patch_w, patch_b, nullptr, y_,
                                     M_FWD, 127, CPATCH);
    build_h<<<(CB0 * CL * CHID + 255) / 256, 256>>>(y_, h_);

    // 2. mixer layers
    for (int layer = 0; layer < CNL; layer++) {
        rmsnorm_kernel<<<M_ALL / 8, 256>>>(h_, ln_w + layer * CHID, u_, M_ALL);
        gemm_tc<0><<<dim3(13, 192), 256>>>(u_, in_w + (size_t)layer * CPROJ * CHID,
                                           in_b + layer * CPROJ, nullptr, proj_,
                                           M_ALL, CPROJ, CHID);
        conv_kernel<<<(CBZ * CL * CCONVD + 255) / 256, 256>>>(
            proj_, conv_w + (size_t)layer * CCONVD * 4, conv_b + layer * CCONVD, xc_);
        dtprep_kernel<<<(CBZ * CL * CNH + 255) / 256, 256>>>(
            proj_, dt_bias + layer * CNH, A_log + layer * CNH, dt_, dA_);
        scan_kernel<<<dim3(2, CNH, CBZ), 256>>>(xc_, dt_, dA_, y_);
        gate_norm_kernel<<<M_ALL, 256>>>(y_, xc_, proj_, Dw + layer * CNH,
                                         gnorm_w + layer * CDIN, g_);
        gemm_tc<1><<<dim3(2, 192), 256>>>(g_, out_w + (size_t)layer * CHID * CDIN,
                                          out_b + layer * CHID, h_, h_,
                                          M_ALL, CHID, CDIN);
    }

    // 3. head
    rmsnorm_kernel<<<M_ALL / 8, 256>>>(h_, fnorm_w, u_, M_ALL);
    merge_kernel<<<(CB0 * CL * CHID + 255) / 256, 256>>>(u_, m_);
    gemm_tc<2><<<dim3(2, 96), 256>>>(m_, r1_w, r1_b, nullptr, u_, M_FWD, CHID, CHID);
    gemm_tc<0><<<dim3(8, 96), 256>>>(u_, r2_w, r2_b, nullptr, proj_, M_FWD, CPATCH, CHID);
    unpatchify<<<(CB0 * CCIN * 340 * 720 + 255) / 256, 256>>>(proj_, (float*)d_out);
}

// round 6
// speedup vs baseline: 2.9132x; 1.0194x over previous
#include <cuda_runtime.h>
#include <cuda_bf16.h>
#include <math.h>
#include <stdint.h>

// ---------------- problem constants ----------------
#define CB0   8
#define CCIN  3
#define CGH   17
#define CGW   90
#define CPH   20
#define CPW   8
#define CHID  128
#define CNL   4
#define CNH   4
#define CHD   64
#define CNST  128
#define CDIN  256      // NH*HD
#define CCONVD 512     // DIN + 2*NSTATE
#define CPROJ 772      // DIN + CONVD + NH
#define CL    1530     // GH*GW
#define CBZ   16       // 2*B0
#define CPATCH 480     // CIN*PH*PW
#define CEPS  1e-5f

#define M_FWD  (CB0*CL)    // 12240
#define M_ALL  (CBZ*CL)    // 24480

#define SCHUNK 18
#define SNCH   (CL / SCHUNK)   // 85 exactly

// ---------------- scratch (static device globals; no runtime alloc) ----------------
__device__ float g_h   [CBZ*CL*CHID];
__device__ float g_u   [CBZ*CL*CHID];
__device__ float g_proj[CBZ*CL*CPROJ];
__device__ float g_xc  [CBZ*CL*CCONVD];
__device__ float g_dt  [CBZ*CL*CNH];
__device__ float g_dA  [CBZ*CL*CNH];
__device__ float g_y   [CBZ*CL*CDIN];
__device__ float g_g   [CBZ*CL*CDIN];
__device__ float g_m   [CB0*CL*CHID];

// ---------------- tf32 / f32x2 helpers ----------------
__device__ __forceinline__ uint32_t f2tf32(float f) {
    uint32_t u;
    asm("cvt.rna.tf32.f32 %0, %1;" : "=r"(u) : "f"(f));
    return u;
}

__device__ __forceinline__ void mma_tf32(float* c, uint32_t a0, uint32_t a1,
                                         uint32_t a2, uint32_t a3,
                                         uint32_t b0, uint32_t b1) {
    asm volatile(
        "mma.sync.aligned.m16n8k8.row.col.f32.tf32.tf32.f32 "
        "{%0,%1,%2,%3},{%4,%5,%6,%7},{%8,%9},{%0,%1,%2,%3};"
        : "+f"(c[0]), "+f"(c[1]), "+f"(c[2]), "+f"(c[3])
        : "r"(a0), "r"(a1), "r"(a2), "r"(a3), "r"(b0), "r"(b1));
}

__device__ __forceinline__ unsigned long long fma_x2(unsigned long long a,
                                                     unsigned long long b,
                                                     unsigned long long c) {
    unsigned long long d;
    asm("fma.rn.f32x2 %0, %1, %2, %3;" : "=l"(d) : "l"(a), "l"(b), "l"(c));
    return d;
}
__device__ __forceinline__ unsigned long long mul_x2(unsigned long long a,
                                                     unsigned long long b) {
    unsigned long long d;
    asm("mul.rn.f32x2 %0, %1, %2;" : "=l"(d) : "l"(a), "l"(b));
    return d;
}
__device__ __forceinline__ unsigned long long add_x2(unsigned long long a,
                                                     unsigned long long b) {
    unsigned long long d;
    asm("add.rn.f32x2 %0, %1, %2;" : "=l"(d) : "l"(a), "l"(b));
    return d;
}
__device__ __forceinline__ unsigned long long pack2(float v) {
    unsigned long long d;
    asm("mov.b64 %0, {%1, %1};" : "=l"(d) : "r"(__float_as_uint(v)));
    return d;
}
__device__ __forceinline__ float unpack_sum(unsigned long long v) {
    uint32_t lo, hi;
    asm("mov.b64 {%0, %1}, %2;" : "=r"(lo), "=r"(hi) : "l"(v));
    return __uint_as_float(lo) + __uint_as_float(hi);
}

// ---------------- tensor-core GEMM: C[M,N] = A[M,K] @ W[N,K]^T + bias ----------------
// MODE 0: +bias;  MODE 1: +bias + residual R;  MODE 2: +bias then exact GELU
// Software-pipelined: next k-tile LDG issued right after barrier, cvt+STS at top.
template<int MODE>
__global__ void __launch_bounds__(256, 2)
gemm_tc(const float* __restrict__ A, const float* __restrict__ W,
        const float* __restrict__ bias, const float* __restrict__ R,
        float* __restrict__ C, int M, int N, int K)
{
    __shared__ uint32_t As[128][36];   // [m][k], stride 36 (144B = 9*16B, aligned)
    __shared__ uint32_t Ws[64][36];    // [n][k]

    const int tid  = threadIdx.x;
    const int warp = tid >> 5;
    const int lane = tid & 31;
    const int g    = lane >> 2;
    const int t    = lane & 3;
    const int wm   = warp >> 2;
    const int wn   = warp & 3;
    const int row0 = blockIdx.y * 128;
    const int col0 = blockIdx.x * 64;

    float acc[4][2][4];
#pragma unroll
    for (int mt = 0; mt < 4; mt++)
#pragma unroll
        for (int nt = 0; nt < 2; nt++)
#pragma unroll
            for (int j = 0; j < 4; j++) acc[mt][nt][j] = 0.f;

    const int kc = (tid & 7) << 2;
    const int rr = tid >> 3;

    float4 pa[4], pw[2];

#define GEMM_LOAD(k0_)                                                                  \
    {                                                                                   \
        _Pragma("unroll")                                                               \
        for (int pass = 0; pass < 4; pass++) {                                          \
            int gr = row0 + rr + pass * 32;                                             \
            pa[pass] = make_float4(0.f, 0.f, 0.f, 0.f);                                 \
            if (gr < M)                                                                 \
                pa[pass] = *reinterpret_cast<const float4*>(&A[(size_t)gr * K + (k0_) + kc]); \
        }                                                                               \
        _Pragma("unroll")                                                               \
        for (int pass = 0; pass < 2; pass++) {                                          \
            int gc = col0 + rr + pass * 32;                                             \
            pw[pass] = make_float4(0.f, 0.f, 0.f, 0.f);                                 \
            if (gc < N)                                                                 \
                pw[pass] = *reinterpret_cast<const float4*>(&W[(size_t)gc * K + (k0_) + kc]); \
        }                                                                               \
    }

    GEMM_LOAD(0);
    const int ktiles = K >> 5;

    for (int kt = 0; kt < ktiles; kt++) {
        // commit staged regs (tf32 convert at staging time, .rna rounding)
#pragma unroll
        for (int pass = 0; pass < 4; pass++)
            *reinterpret_cast<uint4*>(&As[rr + pass * 32][kc]) =
                make_uint4(f2tf32(pa[pass].x), f2tf32(pa[pass].y),
                           f2tf32(pa[pass].z), f2tf32(pa[pass].w));
#pragma unroll
        for (int pass = 0; pass < 2; pass++)
            *reinterpret_cast<uint4*>(&Ws[rr + pass * 32][kc]) =
                make_uint4(f2tf32(pw[pass].x), f2tf32(pw[pass].y),
                           f2tf32(pw[pass].z), f2tf32(pw[pass].w));
        __syncthreads();

        if (kt + 1 < ktiles) GEMM_LOAD((kt + 1) << 5);   // overlap with compute

#pragma unroll
        for (int ks = 0; ks < 4; ks++) {
            const int kb = ks << 3;
            uint32_t b[2][2];
#pragma unroll
            for (int nt = 0; nt < 2; nt++) {
                int n = wn * 16 + nt * 8 + g;
                b[nt][0] = Ws[n][kb + t];
                b[nt][1] = Ws[n][kb + t + 4];
            }
#pragma unroll
            for (int mt = 0; mt < 4; mt++) {
                int m = wm * 64 + mt * 16;
                uint32_t a0 = As[m + g][kb + t];
                uint32_t a1 = As[m + g + 8][kb + t];
                uint32_t a2 = As[m + g][kb + t + 4];
                uint32_t a3 = As[m + g + 8][kb + t + 4];
#pragma unroll
                for (int nt = 0; nt < 2; nt++)
                    mma_tf32(acc[mt][nt], a0, a1, a2, a3, b[nt][0], b[nt][1]);
            }
        }
        __syncthreads();
    }
#undef GEMM_LOAD

#pragma unroll
    for (int mt = 0; mt < 4; mt++) {
        int rl = row0 + wm * 64 + mt * 16 + g;
#pragma unroll
        for (int half = 0; half < 2; half++) {
            int r = rl + half * 8;
            if (r >= M) continue;
#pragma unroll
            for (int nt = 0; nt < 2; nt++) {
                int cb = col0 + wn * 16 + nt * 8 + 2 * t;
#pragma unroll
                for (int j = 0; j < 2; j++) {
                    int c = cb + j;
                    if (c >= N) continue;
                    float v = acc[mt][nt][half * 2 + j] + bias[c];
                    if (MODE == 1) v += R[(size_t)r * N + c];
                    if (MODE == 2) v = 0.5f * v * (1.f + erff(v * 0.70710678118654752f));
                    C[(size_t)r * N + c] = v;
                }
            }
        }
    }
}

// ---------------- patch gather ----------------
__global__ void gather_patches(const float* __restrict__ x, float* __restrict__ Apat)
{
    int idx = blockIdx.x * blockDim.x + threadIdx.x;
    if (idx >= M_FWD * CPATCH) return;
    int col = idx % CPATCH;
    int row = idx / CPATCH;
    int c = col / 160, rem = col % 160;
    int p = rem >> 3, q = rem & 7;
    int b = row / CL, l = row % CL;
    int i = l / CGW, j = l % CGW;
    Apat[idx] = x[(((size_t)b * CCIN + c) * 340 + (i * CPH + p)) * 720 + (j * CPW + q)];
}

// ---------------- build h ----------------
__global__ void build_h(const float* __restrict__ seq, float* __restrict__ h)
{
    int idx = blockIdx.x * blockDim.x + threadIdx.x;
    if (idx >= CB0 * CL * CHID) return;
    int d = idx & 127;
    int l = (idx >> 7) % CL;
    int b = idx / (CL * CHID);
    float v;
    if (d < 127) v = seq[(size_t)(b * CL + l) * 127 + d];
    else         v = (float)(l / CGW) * (1.f / 16.f);
    h[idx] = v;
    h[(size_t)(CB0 + b) * CL * CHID + (size_t)(CL - 1 - l) * CHID + d] = v;
}

// ---------------- RMSNorm over 128 (warp per row) ----------------
__global__ void rmsnorm_kernel(const float* __restrict__ in, const float* __restrict__ w,
                               float* __restrict__ out, int rows)
{
    int warp = blockIdx.x * (blockDim.x >> 5) + (threadIdx.x >> 5);
    if (warp >= rows) return;
    int lane = threadIdx.x & 31;
    float4 v = reinterpret_cast<const float4*>(in + (size_t)warp * CHID)[lane];
    float ss = v.x * v.x + v.y * v.y + v.z * v.z + v.w * v.w;
#pragma unroll
    for (int o = 16; o; o >>= 1) ss += __shfl_xor_sync(0xffffffffu, ss, o);
    float sc = rsqrtf(ss * (1.f / 128.f) + CEPS);
    float4 wv = reinterpret_cast<const float4*>(w)[lane];
    float4 ov = make_float4(v.x * sc * wv.x, v.y * sc * wv.y, v.z * sc * wv.z, v.w * sc * wv.w);
    reinterpret_cast<float4*>(out + (size_t)warp * CHID)[lane] = ov;
}

// ---------------- depthwise causal conv(K=4) + SiLU, float4 per thread ----------------
__global__ void conv_kernel(const float* __restrict__ proj, const float* __restrict__ cw,
                            const float* __restrict__ cb, float* __restrict__ xc)
{
    int idx = blockIdx.x * blockDim.x + threadIdx.x;
    if (idx >= CBZ * CL * (CCONVD / 4)) return;
    int c4 = (idx & 127) << 2;            // channel base (0,4,...,508)
    int l  = (idx >> 7) % CL;
    int b  = idx / (128 * CL);
    const float* pr = proj + (size_t)(b * CL) * CPROJ + CDIN + c4;
    float4 w0 = reinterpret_cast<const float4*>(cw)[c4 + 0];
    float4 w1 = reinterpret_cast<const float4*>(cw)[c4 + 1];
    float4 w2 = reinterpret_cast<const float4*>(cw)[c4 + 2];
    float4 w3 = reinterpret_cast<const float4*>(cw)[c4 + 3];
    float4 s = reinterpret_cast<const float4*>(cb)[c4 >> 2];
#pragma unroll
    for (int k = 0; k < 4; k++) {
        int ls = l - 3 + k;
        if (ls >= 0) {
            float4 v = *reinterpret_cast<const float4*>(&pr[(size_t)ls * CPROJ]);
            float tw0 = (&w0.x)[k], tw1 = (&w1.x)[k], tw2 = (&w2.x)[k], tw3 = (&w3.x)[k];
            s.x += tw0 * v.x; s.y += tw1 * v.y; s.z += tw2 * v.z; s.w += tw3 * v.w;
        }
    }
    s.x = s.x / (1.f + __expf(-s.x));
    s.y = s.y / (1.f + __expf(-s.y));
    s.z = s.z / (1.f + __expf(-s.z));
    s.w = s.w / (1.f + __expf(-s.w));
    reinterpret_cast<float4*>(xc)[idx] = s;
}

// ---------------- dt prep ----------------
__global__ void dtprep_kernel(const float* __restrict__ proj, const float* __restrict__ dtb,
                              const float* __restrict__ alog, float* __restrict__ dt,
                              float* __restrict__ dA)
{
    int idx = blockIdx.x * blockDim.x + threadIdx.x;
    if (idx >= CBZ * CL * CNH) return;
    int h = idx & 3;
    int token = idx >> 2;
    float xv = proj[(size_t)token * CPROJ + (CDIN + CCONVD) + h] + dtb[h];
    float sp = (xv > 20.f) ? xv : log1pf(__expf(xv));
    dt[idx] = sp;
    dA[idx] = __expf(-__expf(alog[h]) * sp);
}

// ---------------- SSM scan v3: chunked cp.async + packed f32x2 math ----------------
__global__ void __launch_bounds__(256)
scan_kernel(const float* __restrict__ xc, const float* __restrict__ dt,
            const float* __restrict__ dA, float* __restrict__ y)
{
    const int pg = blockIdx.x;
    const int h  = blockIdx.y;
    const int b  = blockIdx.z;
    const int tid = threadIdx.x;
    const int p_local = tid >> 3;
    const int noct    = tid & 7;
    const int nb      = noct << 4;

    __shared__ __align__(16) float sBC[2][SCHUNK][288];
    __shared__ __align__(16) float sX [2][SCHUNK][32];
    __shared__ float sDT[2][SCHUNK];
    __shared__ float sDA[2][SCHUNK];

    const float* xcb = xc + (size_t)b * CL * CCONVD;
    const float* dtb = dt + ((size_t)b * CL) * CNH + h;
    const float* dAb = dA + ((size_t)b * CL) * CNH + h;
    float* yb = y + (size_t)b * CL * CDIN + h * CHD + pg * 32;
    const int xoff = h * CHD + pg * 32;

    unsigned long long s2[8];
#pragma unroll
    for (int i = 0; i < 8; i++) s2[i] = 0ull;

    const int gB = ((nb >> 5) * 36) + (nb & 31);
    const int gC = (((nb + 128) >> 5) * 36) + ((nb + 128) & 31);

#define SCAN_ISSUE(cc)                                                              \
    {                                                                               \
        const int buf_ = (cc) & 1;                                                  \
        const int t0_  = (cc) * SCHUNK;                                             \
        for (int i = tid; i < SCHUNK * 64; i += 256) {                              \
            int tt = i >> 6, n0 = (i & 63) << 2;                                    \
            int doff = ((n0 >> 5) * 36) + (n0 & 31);                                \
            uint32_t da = (uint32_t)__cvta_generic_to_shared(&sBC[buf_][tt][doff]); \
            const float* src = xcb + (size_t)(t0_ + tt) * CCONVD + CDIN + n0;       \
            asm volatile("cp.async.ca.shared.global [%0], [%1], 16;" :: "r"(da), "l"(src)); \
        }                                                                           \
        for (int i = tid; i < SCHUNK * 8; i += 256) {                               \
            int tt = i >> 3, n0 = (i & 7) << 2;                                     \
            uint32_t da = (uint32_t)__cvta_generic_to_shared(&sX[buf_][tt][n0]);    \
            const float* src = xcb + (size_t)(t0_ + tt) * CCONVD + xoff + n0;       \
            asm volatile("cp.async.ca.shared.global [%0], [%1], 16;" :: "r"(da), "l"(src)); \
        }                                                                           \
        if (tid < SCHUNK) {                                                         \
            uint32_t da = (uint32_t)__cvta_generic_to_shared(&sDT[buf_][tid]);      \
            const float* src = dtb + (size_t)(t0_ + tid) * CNH;                     \
            asm volatile("cp.async.ca.shared.global [%0], [%1], 4;" :: "r"(da), "l"(src)); \
            uint32_t da2 = (uint32_t)__cvta_generic_to_shared(&sDA[buf_][tid]);     \
            const float* src2 = dAb + (size_t)(t0_ + tid) * CNH;                    \
            asm volatile("cp.async.ca.shared.global [%0], [%1], 4;" :: "r"(da2), "l"(src2)); \
        }                                                                           \
        asm volatile("cp.async.commit_group;");                                     \
    }

    SCAN_ISSUE(0);

    for (int c = 0; c < SNCH; c++) {
        asm volatile("cp.async.wait_group 0;");
        __syncthreads();
        if (c + 1 < SNCH) SCAN_ISSUE(c + 1);
        const int buf = c & 1;
        const int t0 = c * SCHUNK;
#pragma unroll 6
        for (int tt = 0; tt < SCHUNK; tt++) {
            const unsigned long long a2  = pack2(sDA[buf][tt]);
            const unsigned long long sc2 = pack2(sDT[buf][tt] * sX[buf][tt][p_local]);
            const float* base = &sBC[buf][tt][0];
            unsigned long long accA = 0ull, accB = 0ull;
#pragma unroll
            for (int q = 0; q < 4; q++) {
                ulonglong2 bq = *reinterpret_cast<const ulonglong2*>(base + gB + 4 * q);
                ulonglong2 cq = *reinterpret_cast<const ulonglong2*>(base + gC + 4 * q);
                s2[2*q]   = fma_x2(a2, s2[2*q],   mul_x2(sc2, bq.x));
                s2[2*q+1] = fma_x2(a2, s2[2*q+1], mul_x2(sc2, bq.y));
                accA = fma_x2(s2[2*q],   cq.x, accA);
                accB = fma_x2(s2[2*q+1], cq.y, accB);
            }
            float acc = unpack_sum(add_x2(accA, accB));
            acc += __shfl_xor_sync(0xffffffffu, acc, 1);
            acc += __shfl_xor_sync(0xffffffffu, acc, 2);
            acc += __shfl_xor_sync(0xffffffffu, acc, 4);
            if (noct == 0) yb[(size_t)(t0 + tt) * CDIN + p_local] = acc;
        }
    }
#undef SCAN_ISSUE
}

// ---------------- gate+norm: warp per token, float4x2 per lane ----------------
__global__ void gate_norm_kernel(const float* __restrict__ y, const float* __restrict__ xc,
                                 const float* __restrict__ proj, const float* __restrict__ Dv,
                                 const float* __restrict__ gw, float* __restrict__ out)
{
    int token = blockIdx.x * 8 + (threadIdx.x >> 5);
    int lane = threadIdx.x & 31;
    const float4* yrow = reinterpret_cast<const float4*>(y + (size_t)token * CDIN);
    const float4* xrow = reinterpret_cast<const float4*>(xc + (size_t)token * CCONVD);
    const float4* zrow = reinterpret_cast<const float4*>(proj + (size_t)token * CPROJ);
    float4 ya = yrow[lane],      yb2 = yrow[lane + 32];
    float4 xa = xrow[lane],      xb  = xrow[lane + 32];
    float4 za = zrow[lane],      zb  = zrow[lane + 32];
    float Da = Dv[lane >> 4];
    float Db = Dv[2 + (lane >> 4)];

    float4 va, vb;
    va.x = (ya.x + Da * xa.x) * (za.x / (1.f + __expf(-za.x)));
    va.y = (ya.y + Da * xa.y) * (za.y / (1.f + __expf(-za.y)));
    va.z = (ya.z + Da * xa.z) * (za.z / (1.f + __expf(-za.z)));
    va.w = (ya.w + Da * xa.w) * (za.w / (1.f + __expf(-za.w)));
    vb.x = (yb2.x + Db * xb.x) * (zb.x / (1.f + __expf(-zb.x)));
    vb.y = (yb2.y + Db * xb.y) * (zb.y / (1.f + __expf(-zb.y)));
    vb.z = (yb2.z + Db * xb.z) * (zb.z / (1.f + __expf(-zb.z)));
    vb.w = (yb2.w + Db * xb.w) * (zb.w / (1.f + __expf(-zb.w)));

    float ss = va.x*va.x + va.y*va.y + va.z*va.z + va.w*va.w
             + vb.x*vb.x + vb.y*vb.y + vb.z*vb.z + vb.w*vb.w;
#pragma unroll
    for (int o = 16; o; o >>= 1) ss += __shfl_xor_sync(0xffffffffu, ss, o);
    float sc = rsqrtf(ss * (1.f / 256.f) + CEPS);

    float4 ga = reinterpret_cast<const float4*>(gw)[lane];
    float4 gb = reinterpret_cast<const float4*>(gw)[lane + 32];
    float4 oa = make_float4(va.x*sc*ga.x, va.y*sc*ga.y, va.z*sc*ga.z, va.w*sc*ga.w);
    float4 ob = make_float4(vb.x*sc*gb.x, vb.y*sc*gb.y, vb.z*sc*gb.z, vb.w*sc*gb.w);
    float4* orow = reinterpret_cast<float4*>(out + (size_t)token * CDIN);
    orow[lane] = oa;
    orow[lane + 32] = ob;
}

// ---------------- merge fwd/bwd halves ----------------
__global__ void merge_kernel(const float* __restrict__ u, float* __restrict__ m)
{
    int idx = blockIdx.x * blockDim.x + threadIdx.x;
    if (idx >= CB0 * CL * CHID) return;
    int d = idx & 127;
    int l = (idx >> 7) % CL;
    int b = idx / (CL * CHID);
    float a = u[idx];
    float c = u[(size_t)(CB0 + b) * CL * CHID + (size_t)(CL - 1 - l) * CHID + d];
    m[idx] = 0.5f * (a + c);
}

// ---------------- un-patchify ----------------
__global__ void unpatchify(const float* __restrict__ r, float* __restrict__ out)
{
    int idx = blockIdx.x * blockDim.x + threadIdx.x;
    if (idx >= CB0 * CCIN * 340 * 720) return;
    int ww = idx % 720;
    int t  = idx / 720;
    int hh = t % 340; t /= 340;
    int c  = t % CCIN;
    int b  = t / CCIN;
    int i = hh / CPH, p = hh % CPH;
    int j = ww / CPW, q = ww % CPW;
    out[idx] = r[(size_t)(b * CL + i * CGW + j) * CPATCH + (p * CPW + q) * CCIN + c];
}

// ---------------- launcher ----------------
extern "C" void kernel_launch(void* const* d_in, const int* in_sizes, int n_in,
                              void* d_out, int out_size)
{
    const float* x        = (const float*)d_in[0];
    const float* patch_w  = (const float*)d_in[1];
    const float* patch_b  = (const float*)d_in[2];
    const float* ln_w     = (const float*)d_in[3];
    const float* in_w     = (const float*)d_in[4];
    const float* in_b     = (const float*)d_in[5];
    const float* conv_w   = (const float*)d_in[6];
    const float* conv_b   = (const float*)d_in[7];
    const float* dt_bias  = (const float*)d_in[8];
    const float* A_log    = (const float*)d_in[9];
    const float* Dw       = (const float*)d_in[10];
    const float* gnorm_w  = (const float*)d_in[11];
    const float* out_w    = (const float*)d_in[12];
    const float* out_b    = (const float*)d_in[13];
    const float* fnorm_w  = (const float*)d_in[14];
    const float* r1_w     = (const float*)d_in[15];
    const float* r1_b     = (const float*)d_in[16];
    const float* r2_w     = (const float*)d_in[17];
    const float* r2_b     = (const float*)d_in[18];

    float *h_, *u_, *proj_, *xc_, *dt_, *dA_, *y_, *g_, *m_;
    cudaGetSymbolAddress((void**)&h_,    g_h);
    cudaGetSymbolAddress((void**)&u_,    g_u);
    cudaGetSymbolAddress((void**)&proj_, g_proj);
    cudaGetSymbolAddress((void**)&xc_,   g_xc);
    cudaGetSymbolAddress((void**)&dt_,   g_dt);
    cudaGetSymbolAddress((void**)&dA_,   g_dA);
    cudaGetSymbolAddress((void**)&y_,    g_y);
    cudaGetSymbolAddress((void**)&g_,    g_g);
    cudaGetSymbolAddress((void**)&m_,    g_m);

    // 1. patch embedding
    gather_patches<<<(M_FWD * CPATCH + 255) / 256, 256>>>(x, proj_);
    gemm_tc<0><<<dim3(2, 96), 256>>>(proj_, patch_w, patch_b, nullptr, y_,
                                     M_FWD, 127, CPATCH);
    build_h<<<(CB0 * CL * CHID + 255) / 256, 256>>>(y_, h_);

    // 2. mixer layers
    for (int layer = 0; layer < CNL; layer++) {
        rmsnorm_kernel<<<M_ALL / 8, 256>>>(h_, ln_w + layer * CHID, u_, M_ALL);
        gemm_tc<0><<<dim3(13, 192), 256>>>(u_, in_w + (size_t)layer * CPROJ * CHID,
                                           in_b + layer * CPROJ, nullptr, proj_,
                                           M_ALL, CPROJ, CHID);
        conv_kernel<<<(CBZ * CL * 128 + 255) / 256, 256>>>(
            proj_, conv_w + (size_t)layer * CCONVD * 4, conv_b + layer * CCONVD, xc_);
        dtprep_kernel<<<(CBZ * CL * CNH + 255) / 256, 256>>>(
            proj_, dt_bias + layer * CNH, A_log + layer * CNH, dt_, dA_);
        scan_kernel<<<dim3(2, CNH, CBZ), 256>>>(xc_, dt_, dA_, y_);
        gate_norm_kernel<<<M_ALL / 8, 256>>>(y_, xc_, proj_, Dw + layer * CNH,
                                             gnorm_w + layer * CDIN, g_);
        gemm_tc<1><<<dim3(2, 192), 256>>>(g_, out_w + (size_t)layer * CHID * CDIN,
                                          out_b + layer * CHID, h_, h_,
                                          M_ALL, CHID, CDIN);
    }

    // 3. head
    rmsnorm_kernel<<<M_ALL / 8, 256>>>(h_, fnorm_w, u_, M_ALL);
    merge_kernel<<<(CB0 * CL * CHID + 255) / 256, 256>>>(u_, m_);
    gemm_tc<2><<<dim3(2, 96), 256>>>(m_, r1_w, r1_b, nullptr, u_, M_FWD, CHID, CHID);
    gemm_tc<0><<<dim3(8, 96), 256>>>(u_, r2_w, r2_b, nullptr, proj_, M_FWD, CPATCH, CHID);
    unpatchify<<<(CB0 * CCIN * 340 * 720 + 255) / 256, 256>>>(proj_, (float*)d_out);
}